// round 9
// baseline (speedup 1.0000x reference)
#include <cuda_runtime.h>
#include <cuda_bf16.h>
#include <cstdint>

#define B_DIM  2048
#define NVIS   2048
#define NHID   1024
#define NCLASS 64

// ---------------------------------------------------------------------------
// Static device scratch (no allocation allowed)
// ---------------------------------------------------------------------------
__device__ float g_pre[B_DIM * NHID];                 // 8 MB
__device__ __nv_bfloat16 g_vh[B_DIM * NVIS];          // 8 MB
__device__ __nv_bfloat16 g_vm[B_DIM * NVIS];          // 8 MB
__device__ __nv_bfloat16 g_wh[NHID * NVIS];           // 4 MB (W^T limbs, [n][k])
__device__ __nv_bfloat16 g_wm[NHID * NVIS];           // 4 MB

__device__ __forceinline__ uint32_t smem_u32(const void* p) {
    uint32_t a;
    asm("{ .reg .u64 t; cvta.to.shared.u64 t, %1; cvt.u32.u64 %0, t; }" : "=r"(a) : "l"(p));
    return a;
}

// ---------------------------------------------------------------------------
// K0: fused split kernel (unchanged; ~10.2us)
// ---------------------------------------------------------------------------
__global__ __launch_bounds__(256) void split_kernel(const float* __restrict__ v,
                                                    const float* __restrict__ W) {
    if (blockIdx.x < 1024) {
        const int base = blockIdx.x * 1024 + threadIdx.x;   // float4 index
        float4 x[4];
#pragma unroll
        for (int r = 0; r < 4; r++)
            x[r] = *(const float4*)(v + (size_t)(base + r * 256) * 4);
#pragma unroll
        for (int r = 0; r < 4; r++) {
            float xs[4] = {x[r].x, x[r].y, x[r].z, x[r].w};
            __nv_bfloat16 hb[4], mb[4];
#pragma unroll
            for (int i = 0; i < 4; i++) {
                hb[i] = __float2bfloat16(xs[i]);
                mb[i] = __float2bfloat16(xs[i] - __bfloat162float(hb[i]));
            }
            size_t o = (size_t)(base + r * 256) * 4;
            *(uint2*)(g_vh + o) = *(uint2*)hb;
            *(uint2*)(g_vm + o) = *(uint2*)mb;
        }
    } else {
        __shared__ float s[32][33];
        int bid = blockIdx.x - 1024;
        int nb = (bid & 31) * 32;
        int kb = (bid >> 5) * 32;
        int tx = threadIdx.x & 31;
        int ty = threadIdx.x >> 5;
        float w[4];
#pragma unroll
        for (int i = 0; i < 4; i++)
            w[i] = W[(size_t)(kb + ty + i * 8) * NHID + nb + tx];
#pragma unroll
        for (int i = 0; i < 4; i++)
            s[ty + i * 8][tx] = w[i];
        __syncthreads();
#pragma unroll
        for (int i = 0; i < 4; i++) {
            int n = ty + i * 8;
            float x = s[tx][n];
            __nv_bfloat16 h = __float2bfloat16(x);
            __nv_bfloat16 m = __float2bfloat16(x - __bfloat162float(h));
            size_t o = (size_t)(nb + n) * NVIS + kb + tx;
            g_wh[o] = h; g_wm[o] = m;
        }
    }
}

// ---------------------------------------------------------------------------
// K1: pre = v @ W + c  via mma.sync bf16, 2-limb split, 3 products (hh,hm,mh)
// CTA 128x64, KC=32, 3-stage cp.async pipeline, 90KB SMEM -> 2 CTAs/SM.
// Grid 16x16 = 256 CTAs. 8 warps, warp tile 32x32.
// ---------------------------------------------------------------------------
#define KC        32
#define ROWB      80                     // 64B data + 16B pad
#define TILEA     (128 * ROWB)           // 10240 (v limb tiles: 128 rows)
#define TILEW     (64  * ROWB)           // 5120  (w limb tiles: 64 rows)
#define BUFB      (2 * TILEA + 2 * TILEW)// 30720
#define STAGES    3
#define GEMM_SMEM (STAGES * BUFB)        // 92160 -> 2 CTAs/SM

#define CP_ASYNC(dst, src) \
    asm volatile("cp.async.cg.shared.global [%0], [%1], 16;" :: "r"(dst), "l"(src))
#define CP_COMMIT() asm volatile("cp.async.commit_group;" ::: "memory")
#define CP_WAIT(n)  asm volatile("cp.async.wait_group %0;" :: "n"(n) : "memory")

#define LDSM_X4(r0, r1, r2, r3, a) \
    asm volatile("ldmatrix.sync.aligned.m8n8.x4.shared.b16 {%0,%1,%2,%3}, [%4];" \
        : "=r"(r0), "=r"(r1), "=r"(r2), "=r"(r3) : "r"(a))

#define MMA16816(c0, c1, c2, c3, a0, a1, a2, a3, b0, b1) \
    asm volatile("mma.sync.aligned.m16n8k16.row.col.f32.bf16.bf16.f32 " \
        "{%0,%1,%2,%3}, {%4,%5,%6,%7}, {%8,%9}, {%0,%1,%2,%3};" \
        : "+f"(c0), "+f"(c1), "+f"(c2), "+f"(c3) \
        : "r"(a0), "r"(a1), "r"(a2), "r"(a3), "r"(b0), "r"(b1))

__global__ __launch_bounds__(256, 2) void gemm_mma_kernel(const float* __restrict__ cvec) {
    extern __shared__ char smem[];
    const int tid  = threadIdx.x;
    const int wid  = tid >> 5;
    const int lane = tid & 31;
    const int block_row = blockIdx.y * 128;   // batch (M)
    const int block_col = blockIdx.x * 64;    // hidden (N)

    // one K-chunk (KC=32 cols = 64B/row): A tiles 128x4 16B-chunks, W tiles 64x4
    auto load_chunk = [&](int k0, int stage) {
        char* bufp = smem + stage * BUFB;
#pragma unroll
        for (int t = 0; t < 2; t++) {
            const __nv_bfloat16* src = t ? g_vm : g_vh;
#pragma unroll
            for (int i = 0; i < 2; i++) {
                int idx = i * 256 + tid;          // 0..511
                int r = idx >> 2, c = idx & 3;
                CP_ASYNC(smem_u32(bufp + t * TILEA + r * ROWB + c * 16),
                         src + (size_t)(block_row + r) * NVIS + k0 + c * 8);
            }
        }
#pragma unroll
        for (int t = 0; t < 2; t++) {
            const __nv_bfloat16* src = t ? g_wm : g_wh;
            {
                int idx = tid;                    // 0..255
                int r = idx >> 2, c = idx & 3;
                CP_ASYNC(smem_u32(bufp + 2 * TILEA + t * TILEW + r * ROWB + c * 16),
                         src + (size_t)(block_col + r) * NVIS + k0 + c * 8);
            }
        }
    };

    // warp tile: 32 (M) x 32 (N)
    const int m_off = (wid & 3) * 32;
    const int n_off = (wid >> 2) * 32;

    const uint32_t a_lane = (uint32_t)(m_off + (lane & 15)) * ROWB + (lane >> 4) * 16;
    const uint32_t b_lane = (uint32_t)(n_off + ((lane >> 4) & 1) * 8 + (lane & 7)) * ROWB
                          + ((lane >> 3) & 1) * 16;

    float acc[2][4][4];
#pragma unroll
    for (int mi = 0; mi < 2; mi++)
#pragma unroll
        for (int ni = 0; ni < 4; ni++)
#pragma unroll
            for (int q = 0; q < 4; q++) acc[mi][ni][q] = 0.0f;

    const int NCHUNK = NVIS / KC;   // 64

    load_chunk(0, 0);      CP_COMMIT();
    load_chunk(KC, 1);     CP_COMMIT();

    for (int ch = 0; ch < NCHUNK; ch++) {
        if (ch + 2 < NCHUNK) { load_chunk((ch + 2) * KC, (ch + 2) % STAGES); CP_COMMIT(); }
        if (ch + 2 < NCHUNK)      { CP_WAIT(2); }
        else if (ch + 1 < NCHUNK) { CP_WAIT(1); }
        else                      { CP_WAIT(0); }
        __syncthreads();

        const char* bufp = smem + (ch % STAGES) * BUFB;
        const uint32_t a_base0 = smem_u32(bufp) + a_lane;                 // vh
        const uint32_t a_base1 = a_base0 + TILEA;                         // vm
        const uint32_t b_base0 = smem_u32(bufp + 2 * TILEA) + b_lane;     // wh
        const uint32_t b_base1 = b_base0 + TILEW;                         // wm

#pragma unroll
        for (int ks = 0; ks < KC / 16; ks++) {
            uint32_t Af[2][2][4];
            uint32_t Bf[2][4][2];
#pragma unroll
            for (int mi = 0; mi < 2; mi++) {
                LDSM_X4(Af[0][mi][0], Af[0][mi][1], Af[0][mi][2], Af[0][mi][3],
                        a_base0 + (uint32_t)mi * 16 * ROWB + ks * 32);
                LDSM_X4(Af[1][mi][0], Af[1][mi][1], Af[1][mi][2], Af[1][mi][3],
                        a_base1 + (uint32_t)mi * 16 * ROWB + ks * 32);
            }
#pragma unroll
            for (int g = 0; g < 2; g++) {
                LDSM_X4(Bf[0][2*g][0], Bf[0][2*g][1], Bf[0][2*g+1][0], Bf[0][2*g+1][1],
                        b_base0 + (uint32_t)g * 16 * ROWB + ks * 32);
                LDSM_X4(Bf[1][2*g][0], Bf[1][2*g][1], Bf[1][2*g+1][0], Bf[1][2*g+1][1],
                        b_base1 + (uint32_t)g * 16 * ROWB + ks * 32);
            }
#pragma unroll
            for (int mi = 0; mi < 2; mi++)
#pragma unroll
                for (int ni = 0; ni < 4; ni++) {
                    MMA16816(acc[mi][ni][0], acc[mi][ni][1], acc[mi][ni][2], acc[mi][ni][3],
                             Af[0][mi][0], Af[0][mi][1], Af[0][mi][2], Af[0][mi][3],
                             Bf[0][ni][0], Bf[0][ni][1]);
                    MMA16816(acc[mi][ni][0], acc[mi][ni][1], acc[mi][ni][2], acc[mi][ni][3],
                             Af[0][mi][0], Af[0][mi][1], Af[0][mi][2], Af[0][mi][3],
                             Bf[1][ni][0], Bf[1][ni][1]);
                    MMA16816(acc[mi][ni][0], acc[mi][ni][1], acc[mi][ni][2], acc[mi][ni][3],
                             Af[1][mi][0], Af[1][mi][1], Af[1][mi][2], Af[1][mi][3],
                             Bf[0][ni][0], Bf[0][ni][1]);
                }
        }
        __syncthreads();
    }

#pragma unroll
    for (int mi = 0; mi < 2; mi++) {
        const int r0 = block_row + m_off + mi * 16 + (lane >> 2);
        const int r1 = r0 + 8;
#pragma unroll
        for (int ni = 0; ni < 4; ni++) {
            const int col = block_col + n_off + ni * 8 + (lane & 3) * 2;
            const float c0 = __ldg(cvec + col);
            const float c1 = __ldg(cvec + col + 1);
            float2 o0 = {acc[mi][ni][0] + c0, acc[mi][ni][1] + c1};
            float2 o1 = {acc[mi][ni][2] + c0, acc[mi][ni][3] + c1};
            *(float2*)(g_pre + (size_t)r0 * NHID + col) = o0;
            *(float2*)(g_pre + (size_t)r1 * NHID + col) = o1;
        }
    }
}

// ---------------------------------------------------------------------------
// K2: two-pass fenergy (unchanged)
// ---------------------------------------------------------------------------
#define TJ 128
#define UPAD 133

__global__ __launch_bounds__(256) void fenergy_kernel(const float* __restrict__ dvec,
                                                      const float* __restrict__ U,
                                                      float* __restrict__ out) {
    __shared__ float  Us[64 * UPAD];
    __shared__ float  ps[8][TJ];
    __shared__ float2 slist[8][TJ];

    const int tid  = threadIdx.x;
    const int wid  = tid >> 5;
    const int lane = tid & 31;
    const int b0   = blockIdx.x * 8;
    const int y0   = lane;
    const int y1   = lane + 32;

    const float* urow0 = &Us[y0 * UPAD];
    const float* urow1 = &Us[y1 * UPAD];

    const float LOG2E = 1.4426950408889634f;
    const float LN2   = 0.6931471805599453f;

    float acc0 = 0.0f, acc1 = 0.0f;

    for (int j0 = 0; j0 < NHID; j0 += TJ) {
#pragma unroll
        for (int i = 0; i < 8; i++) {
            int e  = i * 256 + tid;
            int yy = e >> 5;
            int jq = (e & 31) * 4;
            float4 u4 = *(const float4*)(U + (size_t)yy * NHID + j0 + jq);
            float* dst = &Us[yy * UPAD + jq];
            dst[0] = u4.x; dst[1] = u4.y; dst[2] = u4.z; dst[3] = u4.w;
        }
        {
            int e  = tid;
            int bb = e >> 5;
            int jq = (e & 31) * 4;
            float4 p4 = *(const float4*)(g_pre + (size_t)(b0 + bb) * NHID + j0 + jq);
            *(float4*)&ps[bb][jq] = p4;
        }
        __syncthreads();

        int cnt = 0;
#pragma unroll
        for (int s = 0; s < 4; s++) {
            int jj = s * 32 + lane;
            float p = ps[wid][jj];
            bool slow = fabsf(p) < 21.0f;
            unsigned mask = __ballot_sync(0xffffffffu, slow);
            int rank = __popc(mask & ((1u << lane) - 1u));
            if (slow) slist[wid][cnt + rank] = make_float2(__int_as_float(jj), p);
            cnt += __popc(mask);
        }

        float t0a = 0.f, t0b = 0.f, t1a = 0.f, t1b = 0.f;
#pragma unroll 8
        for (int jj = 0; jj < TJ; jj += 4) {
            float4 pv = *(const float4*)&ps[wid][jj];
            t0a += fmaxf(pv.x + urow0[jj + 0], 0.f);
            t0b += fmaxf(pv.y + urow0[jj + 1], 0.f);
            t0a += fmaxf(pv.z + urow0[jj + 2], 0.f);
            t0b += fmaxf(pv.w + urow0[jj + 3], 0.f);
            t1a += fmaxf(pv.x + urow1[jj + 0], 0.f);
            t1b += fmaxf(pv.y + urow1[jj + 1], 0.f);
            t1a += fmaxf(pv.z + urow1[jj + 2], 0.f);
            t1b += fmaxf(pv.w + urow1[jj + 3], 0.f);
        }

        float c0 = 0.f, c1 = 0.f;
        float P0 = 1.f, P1 = 1.f;
        for (int i = 0; i < cnt; i++) {
            float2 e = slist[wid][i];
            int jj  = __float_as_int(e.x);
            float p = e.y;
            float u0 = exp2f(-fabsf(p + urow0[jj]) * LOG2E);
            float u1 = exp2f(-fabsf(p + urow1[jj]) * LOG2E);
            P0 = fmaf(P0, u0, P0);
            P1 = fmaf(P1, u1, P1);
            if ((i & 31) == 31) {
                c0 += __log2f(P0); P0 = 1.f;
                c1 += __log2f(P1); P1 = 1.f;
            }
        }
        c0 += __log2f(P0);
        c1 += __log2f(P1);

        acc0 += (t0a + t0b) + LN2 * c0;
        acc1 += (t1a + t1b) + LN2 * c1;
        __syncthreads();
    }

    float f0 = acc0 + __ldg(dvec + y0);
    float f1 = acc1 + __ldg(dvec + y1);

    float m = fmaxf(f0, f1);
#pragma unroll
    for (int o = 16; o > 0; o >>= 1) m = fmaxf(m, __shfl_xor_sync(0xffffffffu, m, o));
    float e0 = __expf(f0 - m);
    float e1 = __expf(f1 - m);
    float s = e0 + e1;
#pragma unroll
    for (int o = 16; o > 0; o >>= 1) s += __shfl_xor_sync(0xffffffffu, s, o);
    float inv = 1.0f / s;
    float p0 = e0 * inv;
    float p1 = e1 * inv;

    float pm = p0; int im = y0;
    if (p1 > pm) { pm = p1; im = y1; }
#pragma unroll
    for (int o = 16; o > 0; o >>= 1) {
        float po = __shfl_xor_sync(0xffffffffu, pm, o);
        int   io = __shfl_xor_sync(0xffffffffu, im, o);
        if (po > pm || (po == pm && io < im)) { pm = po; im = io; }
    }

    const int b = b0 + wid;
    out[(size_t)b * NCLASS + y0] = p0;
    out[(size_t)b * NCLASS + y1] = p1;
    float* oh = out + (size_t)B_DIM * NCLASS;
    oh[(size_t)b * NCLASS + y0] = (y0 == im) ? 1.0f : 0.0f;
    oh[(size_t)b * NCLASS + y1] = (y1 == im) ? 1.0f : 0.0f;
}

// ---------------------------------------------------------------------------
extern "C" void kernel_launch(void* const* d_in, const int* in_sizes, int n_in,
                              void* d_out, int out_size) {
    const float* v = (const float*)d_in[0];
    const float* W = (const float*)d_in[1];
    const float* c = (const float*)d_in[2];
    const float* d = (const float*)d_in[3];
    const float* U = (const float*)d_in[4];
    float* out = (float*)d_out;

    cudaFuncSetAttribute(gemm_mma_kernel,
                         cudaFuncAttributeMaxDynamicSharedMemorySize, GEMM_SMEM);

    split_kernel<<<3072, 256>>>(v, W);
    gemm_mma_kernel<<<dim3(NHID / 64, B_DIM / 128), 256, GEMM_SMEM>>>(c);
    fenergy_kernel<<<B_DIM / 8, 256>>>(d, U, out);
}

// round 10
// speedup vs baseline: 1.0296x; 1.0296x over previous
#include <cuda_runtime.h>
#include <cuda_bf16.h>
#include <cstdint>

#define B_DIM  2048
#define NVIS   2048
#define NHID   1024
#define NCLASS 64

// ---------------------------------------------------------------------------
// Static device scratch (no allocation allowed)
// ---------------------------------------------------------------------------
__device__ float g_pre[B_DIM * NHID];                 // 8 MB
__device__ __nv_bfloat16 g_vh[B_DIM * NVIS];          // 8 MB
__device__ __nv_bfloat16 g_vm[B_DIM * NVIS];          // 8 MB
__device__ __nv_bfloat16 g_wh[NHID * NVIS];           // 4 MB (W^T limbs, [n][k])
__device__ __nv_bfloat16 g_wm[NHID * NVIS];           // 4 MB

__device__ __forceinline__ uint32_t smem_u32(const void* p) {
    uint32_t a;
    asm("{ .reg .u64 t; cvta.to.shared.u64 t, %1; cvt.u32.u64 %0, t; }" : "=r"(a) : "l"(p));
    return a;
}

// ---------------------------------------------------------------------------
// K0: fused split kernel (unchanged; ~10.2us)
// ---------------------------------------------------------------------------
__global__ __launch_bounds__(256) void split_kernel(const float* __restrict__ v,
                                                    const float* __restrict__ W) {
    if (blockIdx.x < 1024) {
        const int base = blockIdx.x * 1024 + threadIdx.x;   // float4 index
        float4 x[4];
#pragma unroll
        for (int r = 0; r < 4; r++)
            x[r] = *(const float4*)(v + (size_t)(base + r * 256) * 4);
#pragma unroll
        for (int r = 0; r < 4; r++) {
            float xs[4] = {x[r].x, x[r].y, x[r].z, x[r].w};
            __nv_bfloat16 hb[4], mb[4];
#pragma unroll
            for (int i = 0; i < 4; i++) {
                hb[i] = __float2bfloat16(xs[i]);
                mb[i] = __float2bfloat16(xs[i] - __bfloat162float(hb[i]));
            }
            size_t o = (size_t)(base + r * 256) * 4;
            *(uint2*)(g_vh + o) = *(uint2*)hb;
            *(uint2*)(g_vm + o) = *(uint2*)mb;
        }
    } else {
        __shared__ float s[32][33];
        int bid = blockIdx.x - 1024;
        int nb = (bid & 31) * 32;
        int kb = (bid >> 5) * 32;
        int tx = threadIdx.x & 31;
        int ty = threadIdx.x >> 5;
        float w[4];
#pragma unroll
        for (int i = 0; i < 4; i++)
            w[i] = W[(size_t)(kb + ty + i * 8) * NHID + nb + tx];
#pragma unroll
        for (int i = 0; i < 4; i++)
            s[ty + i * 8][tx] = w[i];
        __syncthreads();
#pragma unroll
        for (int i = 0; i < 4; i++) {
            int n = ty + i * 8;
            float x = s[tx][n];
            __nv_bfloat16 h = __float2bfloat16(x);
            __nv_bfloat16 m = __float2bfloat16(x - __bfloat162float(h));
            size_t o = (size_t)(nb + n) * NVIS + kb + tx;
            g_wh[o] = h; g_wm[o] = m;
        }
    }
}

// ---------------------------------------------------------------------------
// K1: pre = v @ W + c  — REVERTED to best measured config (round 6):
// CTA 128x128, KC=64, 3-stage cp.async, 221KB SMEM, grid (8,16), 8 warps,
// warp tile 64x32. This is the HMMA-pipe floor (~72us); proven best.
// ---------------------------------------------------------------------------
#define KC        64
#define ROWB      144
#define TILEB     (128 * ROWB)
#define BUFB      (4 * TILEB)
#define STAGES    3
#define GEMM_SMEM (STAGES * BUFB)        // 221184

#define CP_ASYNC(dst, src) \
    asm volatile("cp.async.cg.shared.global [%0], [%1], 16;" :: "r"(dst), "l"(src))
#define CP_COMMIT() asm volatile("cp.async.commit_group;" ::: "memory")
#define CP_WAIT(n)  asm volatile("cp.async.wait_group %0;" :: "n"(n) : "memory")

#define LDSM_X4(r0, r1, r2, r3, a) \
    asm volatile("ldmatrix.sync.aligned.m8n8.x4.shared.b16 {%0,%1,%2,%3}, [%4];" \
        : "=r"(r0), "=r"(r1), "=r"(r2), "=r"(r3) : "r"(a))

#define MMA16816(c0, c1, c2, c3, a0, a1, a2, a3, b0, b1) \
    asm volatile("mma.sync.aligned.m16n8k16.row.col.f32.bf16.bf16.f32 " \
        "{%0,%1,%2,%3}, {%4,%5,%6,%7}, {%8,%9}, {%0,%1,%2,%3};" \
        : "+f"(c0), "+f"(c1), "+f"(c2), "+f"(c3) \
        : "r"(a0), "r"(a1), "r"(a2), "r"(a3), "r"(b0), "r"(b1))

__global__ __launch_bounds__(256, 1) void gemm_mma_kernel(const float* __restrict__ cvec) {
    extern __shared__ char smem[];
    const int tid  = threadIdx.x;
    const int wid  = tid >> 5;
    const int lane = tid & 31;
    const int block_row = blockIdx.y * 128;
    const int block_col = blockIdx.x * 128;

    const __nv_bfloat16* srcs[4] = {g_vh, g_vm, g_wh, g_wm};

    auto load_chunk = [&](int k0, int stage) {
        char* bufp = smem + stage * BUFB;
#pragma unroll
        for (int t = 0; t < 4; t++) {
            const int row0 = (t < 2) ? block_row : block_col;
            const __nv_bfloat16* src = srcs[t];
#pragma unroll
            for (int i = 0; i < 4; i++) {
                int idx = i * 256 + tid;
                int r = idx >> 3;
                int c = idx & 7;
                const void* g = src + (size_t)(row0 + r) * NVIS + k0 + c * 8;
                uint32_t d = smem_u32(bufp + t * TILEB + r * ROWB + c * 16);
                CP_ASYNC(d, g);
            }
        }
    };

    const int m_off = (wid >> 2) * 64;
    const int n_off = (wid & 3) * 32;

    const uint32_t a_lane = (uint32_t)(m_off + (lane & 15)) * ROWB + (lane >> 4) * 16;
    const uint32_t b_lane = (uint32_t)(n_off + ((lane >> 4) & 1) * 8 + (lane & 7)) * ROWB
                          + ((lane >> 3) & 1) * 16;

    float acc[4][4][4];
#pragma unroll
    for (int mi = 0; mi < 4; mi++)
#pragma unroll
        for (int ni = 0; ni < 4; ni++)
#pragma unroll
            for (int q = 0; q < 4; q++) acc[mi][ni][q] = 0.0f;

    const int NCHUNK = NVIS / KC;

    load_chunk(0, 0); CP_COMMIT();
    load_chunk(KC, 1); CP_COMMIT();

    for (int ch = 0; ch < NCHUNK; ch++) {
        if (ch + 2 < NCHUNK) { load_chunk((ch + 2) * KC, (ch + 2) % STAGES); CP_COMMIT(); }
        if (ch + 2 < NCHUNK)      { CP_WAIT(2); }
        else if (ch + 1 < NCHUNK) { CP_WAIT(1); }
        else                      { CP_WAIT(0); }
        __syncthreads();

        const char* bufp = smem + (ch % STAGES) * BUFB;
        const uint32_t a_base0 = smem_u32(bufp) + a_lane;
        const uint32_t a_base1 = a_base0 + TILEB;
        const uint32_t b_base0 = smem_u32(bufp + 2 * TILEB) + b_lane;
        const uint32_t b_base1 = b_base0 + TILEB;

#pragma unroll
        for (int ks = 0; ks < KC / 16; ks++) {
            uint32_t Af[2][4][4];
            uint32_t Bf[2][4][2];
#pragma unroll
            for (int mi = 0; mi < 4; mi++) {
                LDSM_X4(Af[0][mi][0], Af[0][mi][1], Af[0][mi][2], Af[0][mi][3],
                        a_base0 + (uint32_t)mi * 16 * ROWB + ks * 32);
                LDSM_X4(Af[1][mi][0], Af[1][mi][1], Af[1][mi][2], Af[1][mi][3],
                        a_base1 + (uint32_t)mi * 16 * ROWB + ks * 32);
            }
#pragma unroll
            for (int g = 0; g < 2; g++) {
                LDSM_X4(Bf[0][2*g][0], Bf[0][2*g][1], Bf[0][2*g+1][0], Bf[0][2*g+1][1],
                        b_base0 + (uint32_t)g * 16 * ROWB + ks * 32);
                LDSM_X4(Bf[1][2*g][0], Bf[1][2*g][1], Bf[1][2*g+1][0], Bf[1][2*g+1][1],
                        b_base1 + (uint32_t)g * 16 * ROWB + ks * 32);
            }
#pragma unroll
            for (int mi = 0; mi < 4; mi++)
#pragma unroll
                for (int ni = 0; ni < 4; ni++) {
                    MMA16816(acc[mi][ni][0], acc[mi][ni][1], acc[mi][ni][2], acc[mi][ni][3],
                             Af[0][mi][0], Af[0][mi][1], Af[0][mi][2], Af[0][mi][3],
                             Bf[0][ni][0], Bf[0][ni][1]);
                    MMA16816(acc[mi][ni][0], acc[mi][ni][1], acc[mi][ni][2], acc[mi][ni][3],
                             Af[0][mi][0], Af[0][mi][1], Af[0][mi][2], Af[0][mi][3],
                             Bf[1][ni][0], Bf[1][ni][1]);
                    MMA16816(acc[mi][ni][0], acc[mi][ni][1], acc[mi][ni][2], acc[mi][ni][3],
                             Af[1][mi][0], Af[1][mi][1], Af[1][mi][2], Af[1][mi][3],
                             Bf[0][ni][0], Bf[0][ni][1]);
                }
        }
        __syncthreads();
    }

#pragma unroll
    for (int mi = 0; mi < 4; mi++) {
        const int r0 = block_row + m_off + mi * 16 + (lane >> 2);
        const int r1 = r0 + 8;
#pragma unroll
        for (int ni = 0; ni < 4; ni++) {
            const int col = block_col + n_off + ni * 8 + (lane & 3) * 2;
            const float c0 = __ldg(cvec + col);
            const float c1 = __ldg(cvec + col + 1);
            float2 o0 = {acc[mi][ni][0] + c0, acc[mi][ni][1] + c1};
            float2 o1 = {acc[mi][ni][2] + c0, acc[mi][ni][3] + c1};
            *(float2*)(g_pre + (size_t)r0 * NHID + col) = o0;
            *(float2*)(g_pre + (size_t)r1 * NHID + col) = o1;
        }
    }
}

// ---------------------------------------------------------------------------
// K2: two-pass fenergy, split-j version.
// Grid 512 CTAs x 4 batch rows (wave balance 4-vs-3 instead of 2-vs-1).
// 8 warps: warp = (row = wid&3, half = wid>>2); each warp walks only 64 j's
// per tile (halved serial dep chain). Partial F combined via smem at the end.
// ---------------------------------------------------------------------------
#define TJ 128
#define UPAD 133

__global__ __launch_bounds__(256) void fenergy_kernel(const float* __restrict__ dvec,
                                                      const float* __restrict__ U,
                                                      float* __restrict__ out) {
    __shared__ float  Us[64 * UPAD];        // 34 KB
    __shared__ float  ps[4][TJ];            // 2 KB
    __shared__ float2 slist[8][64];         // 4 KB  (per (row,half) slow list)
    __shared__ float  pacc[2][4][64];       // 2 KB  partial F [half][row][y]

    const int tid  = threadIdx.x;
    const int wid  = tid >> 5;
    const int lane = tid & 31;
    const int row  = wid & 3;               // batch row within CTA
    const int half = wid >> 2;              // j-half: 0 -> [0,64), 1 -> [64,128)
    const int b0   = blockIdx.x * 4;
    const int y0   = lane;
    const int y1   = lane + 32;
    const int jbase = half * 64;

    const float* urow0 = &Us[y0 * UPAD];
    const float* urow1 = &Us[y1 * UPAD];

    const float LOG2E = 1.4426950408889634f;
    const float LN2   = 0.6931471805599453f;

    float acc0 = 0.0f, acc1 = 0.0f;

    for (int j0 = 0; j0 < NHID; j0 += TJ) {
        // ---- fill U tile (64 x 128) with float4 loads ----
#pragma unroll
        for (int i = 0; i < 8; i++) {
            int e  = i * 256 + tid;
            int yy = e >> 5;
            int jq = (e & 31) * 4;
            float4 u4 = *(const float4*)(U + (size_t)yy * NHID + j0 + jq);
            float* dst = &Us[yy * UPAD + jq];
            dst[0] = u4.x; dst[1] = u4.y; dst[2] = u4.z; dst[3] = u4.w;
        }
        // ---- fill p tile (4 x 128): threads 0..127 ----
        if (tid < 128) {
            int bb = tid >> 5;
            int jq = (tid & 31) * 4;
            float4 p4 = *(const float4*)(g_pre + (size_t)(b0 + bb) * NHID + j0 + jq);
            *(float4*)&ps[bb][jq] = p4;
        }
        __syncthreads();

        // ---- build this warp's slow list over its 64 j's (|p| < 21) ----
        int cnt = 0;
#pragma unroll
        for (int s = 0; s < 2; s++) {
            int jj = jbase + s * 32 + lane;
            float p = ps[row][jj];
            bool slow = fabsf(p) < 21.0f;
            unsigned mask = __ballot_sync(0xffffffffu, slow);
            int rank = __popc(mask & ((1u << lane) - 1u));
            if (slow) slist[wid][cnt + rank] = make_float2(__int_as_float(jj), p);
            cnt += __popc(mask);
        }

        // ---- pass 1: branch-free relu-sum over this warp's 64 j ----
        float t0a = 0.f, t0b = 0.f, t1a = 0.f, t1b = 0.f;
#pragma unroll 8
        for (int q = 0; q < 64; q += 4) {
            int jj = jbase + q;
            float4 pv = *(const float4*)&ps[row][jj];
            t0a += fmaxf(pv.x + urow0[jj + 0], 0.f);
            t0b += fmaxf(pv.y + urow0[jj + 1], 0.f);
            t0a += fmaxf(pv.z + urow0[jj + 2], 0.f);
            t0b += fmaxf(pv.w + urow0[jj + 3], 0.f);
            t1a += fmaxf(pv.x + urow1[jj + 0], 0.f);
            t1b += fmaxf(pv.y + urow1[jj + 1], 0.f);
            t1a += fmaxf(pv.z + urow1[jj + 2], 0.f);
            t1b += fmaxf(pv.w + urow1[jj + 3], 0.f);
        }

        // ---- pass 2: log-of-product corrections (1 EX2/elem/class) ----
        float c0 = 0.f, c1 = 0.f;
        float P0 = 1.f, P1 = 1.f;
        for (int i = 0; i < cnt; i++) {
            float2 e = slist[wid][i];
            int jj  = __float_as_int(e.x);
            float p = e.y;
            float u0 = exp2f(-fabsf(p + urow0[jj]) * LOG2E);
            float u1 = exp2f(-fabsf(p + urow1[jj]) * LOG2E);
            P0 = fmaf(P0, u0, P0);
            P1 = fmaf(P1, u1, P1);
            if ((i & 31) == 31) {
                c0 += __log2f(P0); P0 = 1.f;
                c1 += __log2f(P1); P1 = 1.f;
            }
        }
        c0 += __log2f(P0);
        c1 += __log2f(P1);

        acc0 += (t0a + t0b) + LN2 * c0;
        acc1 += (t1a + t1b) + LN2 * c1;
        __syncthreads();
    }

    // ---- combine halves via smem ----
    pacc[half][row][y0] = acc0;
    pacc[half][row][y1] = acc1;
    __syncthreads();

    // ---- warps 0..3: softmax + argmax + one_hot for row wid ----
    if (wid < 4) {
        float f0 = pacc[0][wid][y0] + pacc[1][wid][y0] + __ldg(dvec + y0);
        float f1 = pacc[0][wid][y1] + pacc[1][wid][y1] + __ldg(dvec + y1);

        float m = fmaxf(f0, f1);
#pragma unroll
        for (int o = 16; o > 0; o >>= 1) m = fmaxf(m, __shfl_xor_sync(0xffffffffu, m, o));
        float e0 = __expf(f0 - m);
        float e1 = __expf(f1 - m);
        float s = e0 + e1;
#pragma unroll
        for (int o = 16; o > 0; o >>= 1) s += __shfl_xor_sync(0xffffffffu, s, o);
        float inv = 1.0f / s;
        float p0 = e0 * inv;
        float p1 = e1 * inv;

        float pm = p0; int im = y0;
        if (p1 > pm) { pm = p1; im = y1; }
#pragma unroll
        for (int o = 16; o > 0; o >>= 1) {
            float po = __shfl_xor_sync(0xffffffffu, pm, o);
            int   io = __shfl_xor_sync(0xffffffffu, im, o);
            if (po > pm || (po == pm && io < im)) { pm = po; im = io; }
        }

        const int b = b0 + wid;
        out[(size_t)b * NCLASS + y0] = p0;
        out[(size_t)b * NCLASS + y1] = p1;
        float* oh = out + (size_t)B_DIM * NCLASS;
        oh[(size_t)b * NCLASS + y0] = (y0 == im) ? 1.0f : 0.0f;
        oh[(size_t)b * NCLASS + y1] = (y1 == im) ? 1.0f : 0.0f;
    }
}

// ---------------------------------------------------------------------------
extern "C" void kernel_launch(void* const* d_in, const int* in_sizes, int n_in,
                              void* d_out, int out_size) {
    const float* v = (const float*)d_in[0];
    const float* W = (const float*)d_in[1];
    const float* c = (const float*)d_in[2];
    const float* d = (const float*)d_in[3];
    const float* U = (const float*)d_in[4];
    float* out = (float*)d_out;

    cudaFuncSetAttribute(gemm_mma_kernel,
                         cudaFuncAttributeMaxDynamicSharedMemorySize, GEMM_SMEM);

    split_kernel<<<3072, 256>>>(v, W);
    gemm_mma_kernel<<<dim3(NHID / 128, B_DIM / 128), 256, GEMM_SMEM>>>(c);
    fenergy_kernel<<<B_DIM / 4, 256>>>(d, U, out);
}

// round 11
// speedup vs baseline: 1.1631x; 1.1296x over previous
#include <cuda_runtime.h>
#include <cuda_bf16.h>
#include <cstdint>

#define B_DIM  2048
#define NVIS   2048
#define NHID   1024
#define NCLASS 64

// ---------------------------------------------------------------------------
// Static device scratch
// ---------------------------------------------------------------------------
__device__ float g_pre[B_DIM * NHID];                 // 8 MB
__device__ __nv_bfloat16 g_vh[B_DIM * NVIS];          // 8 MB
__device__ __nv_bfloat16 g_vm[B_DIM * NVIS];          // 8 MB
__device__ __nv_bfloat16 g_wh[NHID * NVIS];           // 4 MB (W^T limbs, [n][k])
__device__ __nv_bfloat16 g_wm[NHID * NVIS];           // 4 MB
__device__ __nv_bfloat16 g_mask[B_DIM * NHID];        // 4 MB  M[b][j] = 1[p>21]
__device__ __nv_bfloat16 g_uh[NCLASS * NHID];         // U limbs [y][j]
__device__ __nv_bfloat16 g_um[NCLASS * NHID];
__device__ __nv_bfloat16 g_ul[NCLASS * NHID];
__device__ float g_G[4 * B_DIM * NCLASS];             // 2 MB  split-K mask-GEMM parts

__device__ __forceinline__ uint32_t smem_u32(const void* p) {
    uint32_t a;
    asm("{ .reg .u64 t; cvta.to.shared.u64 t, %1; cvt.u32.u64 %0, t; }" : "=r"(a) : "l"(p));
    return a;
}

// ---------------------------------------------------------------------------
// K0: fused split kernel: v limbs, W^T limbs, U 3-limb copies
// ---------------------------------------------------------------------------
__global__ __launch_bounds__(256) void split_kernel(const float* __restrict__ v,
                                                    const float* __restrict__ W,
                                                    const float* __restrict__ U) {
    if (blockIdx.x < 1024) {
        const int base = blockIdx.x * 1024 + threadIdx.x;   // float4 index
        float4 x[4];
#pragma unroll
        for (int r = 0; r < 4; r++)
            x[r] = *(const float4*)(v + (size_t)(base + r * 256) * 4);
#pragma unroll
        for (int r = 0; r < 4; r++) {
            float xs[4] = {x[r].x, x[r].y, x[r].z, x[r].w};
            __nv_bfloat16 hb[4], mb[4];
#pragma unroll
            for (int i = 0; i < 4; i++) {
                hb[i] = __float2bfloat16(xs[i]);
                mb[i] = __float2bfloat16(xs[i] - __bfloat162float(hb[i]));
            }
            size_t o = (size_t)(base + r * 256) * 4;
            *(uint2*)(g_vh + o) = *(uint2*)hb;
            *(uint2*)(g_vm + o) = *(uint2*)mb;
        }
    } else if (blockIdx.x < 3072) {
        __shared__ float s[32][33];
        int bid = blockIdx.x - 1024;
        int nb = (bid & 31) * 32;
        int kb = (bid >> 5) * 32;
        int tx = threadIdx.x & 31;
        int ty = threadIdx.x >> 5;
        float w[4];
#pragma unroll
        for (int i = 0; i < 4; i++)
            w[i] = W[(size_t)(kb + ty + i * 8) * NHID + nb + tx];
#pragma unroll
        for (int i = 0; i < 4; i++)
            s[ty + i * 8][tx] = w[i];
        __syncthreads();
#pragma unroll
        for (int i = 0; i < 4; i++) {
            int n = ty + i * 8;
            float x = s[tx][n];
            __nv_bfloat16 h = __float2bfloat16(x);
            __nv_bfloat16 m = __float2bfloat16(x - __bfloat162float(h));
            size_t o = (size_t)(nb + n) * NVIS + kb + tx;
            g_wh[o] = h; g_wm[o] = m;
        }
    } else {
        // U 3-limb split: 16 blocks x 256 threads x 4 float4 = 65536 elems
        const int base = (blockIdx.x - 3072) * 1024 + threadIdx.x;   // float4 index
#pragma unroll
        for (int r = 0; r < 4; r++) {
            int idx = base + r * 256;
            float4 x4 = *(const float4*)(U + (size_t)idx * 4);
            float xs[4] = {x4.x, x4.y, x4.z, x4.w};
            __nv_bfloat16 hb[4], mb[4], lb[4];
#pragma unroll
            for (int i = 0; i < 4; i++) {
                hb[i] = __float2bfloat16(xs[i]);
                float r1 = xs[i] - __bfloat162float(hb[i]);
                mb[i] = __float2bfloat16(r1);
                lb[i] = __float2bfloat16(r1 - __bfloat162float(mb[i]));
            }
            size_t o = (size_t)idx * 4;
            *(uint2*)(g_uh + o) = *(uint2*)hb;
            *(uint2*)(g_um + o) = *(uint2*)mb;
            *(uint2*)(g_ul + o) = *(uint2*)lb;
        }
    }
}

// ---------------------------------------------------------------------------
// Shared GEMM macros
// ---------------------------------------------------------------------------
#define CP_ASYNC(dst, src) \
    asm volatile("cp.async.cg.shared.global [%0], [%1], 16;" :: "r"(dst), "l"(src))
#define CP_COMMIT() asm volatile("cp.async.commit_group;" ::: "memory")
#define CP_WAIT(n)  asm volatile("cp.async.wait_group %0;" :: "n"(n) : "memory")

#define LDSM_X4(r0, r1, r2, r3, a) \
    asm volatile("ldmatrix.sync.aligned.m8n8.x4.shared.b16 {%0,%1,%2,%3}, [%4];" \
        : "=r"(r0), "=r"(r1), "=r"(r2), "=r"(r3) : "r"(a))

#define MMA16816(c0, c1, c2, c3, a0, a1, a2, a3, b0, b1) \
    asm volatile("mma.sync.aligned.m16n8k16.row.col.f32.bf16.bf16.f32 " \
        "{%0,%1,%2,%3}, {%4,%5,%6,%7}, {%8,%9}, {%0,%1,%2,%3};" \
        : "+f"(c0), "+f"(c1), "+f"(c2), "+f"(c3) \
        : "r"(a0), "r"(a1), "r"(a2), "r"(a3), "r"(b0), "r"(b1))

// ---------------------------------------------------------------------------
// K1: pre = v @ W + c  (round-6 proven config) + mask write in epilogue
// ---------------------------------------------------------------------------
#define KC        64
#define ROWB      144
#define TILEB     (128 * ROWB)
#define BUFB      (4 * TILEB)
#define STAGES    3
#define GEMM_SMEM (STAGES * BUFB)        // 221184

__global__ __launch_bounds__(256, 1) void gemm_mma_kernel(const float* __restrict__ cvec) {
    extern __shared__ char smem[];
    const int tid  = threadIdx.x;
    const int wid  = tid >> 5;
    const int lane = tid & 31;
    const int block_row = blockIdx.y * 128;
    const int block_col = blockIdx.x * 128;

    const __nv_bfloat16* srcs[4] = {g_vh, g_vm, g_wh, g_wm};

    auto load_chunk = [&](int k0, int stage) {
        char* bufp = smem + stage * BUFB;
#pragma unroll
        for (int t = 0; t < 4; t++) {
            const int row0 = (t < 2) ? block_row : block_col;
            const __nv_bfloat16* src = srcs[t];
#pragma unroll
            for (int i = 0; i < 4; i++) {
                int idx = i * 256 + tid;
                int r = idx >> 3;
                int c = idx & 7;
                const void* g = src + (size_t)(row0 + r) * NVIS + k0 + c * 8;
                uint32_t d = smem_u32(bufp + t * TILEB + r * ROWB + c * 16);
                CP_ASYNC(d, g);
            }
        }
    };

    const int m_off = (wid >> 2) * 64;
    const int n_off = (wid & 3) * 32;

    const uint32_t a_lane = (uint32_t)(m_off + (lane & 15)) * ROWB + (lane >> 4) * 16;
    const uint32_t b_lane = (uint32_t)(n_off + ((lane >> 4) & 1) * 8 + (lane & 7)) * ROWB
                          + ((lane >> 3) & 1) * 16;

    float acc[4][4][4];
#pragma unroll
    for (int mi = 0; mi < 4; mi++)
#pragma unroll
        for (int ni = 0; ni < 4; ni++)
#pragma unroll
            for (int q = 0; q < 4; q++) acc[mi][ni][q] = 0.0f;

    const int NCHUNK = NVIS / KC;

    load_chunk(0, 0); CP_COMMIT();
    load_chunk(KC, 1); CP_COMMIT();

    for (int ch = 0; ch < NCHUNK; ch++) {
        if (ch + 2 < NCHUNK) { load_chunk((ch + 2) * KC, (ch + 2) % STAGES); CP_COMMIT(); }
        if (ch + 2 < NCHUNK)      { CP_WAIT(2); }
        else if (ch + 1 < NCHUNK) { CP_WAIT(1); }
        else                      { CP_WAIT(0); }
        __syncthreads();

        const char* bufp = smem + (ch % STAGES) * BUFB;
        const uint32_t a_base0 = smem_u32(bufp) + a_lane;
        const uint32_t a_base1 = a_base0 + TILEB;
        const uint32_t b_base0 = smem_u32(bufp + 2 * TILEB) + b_lane;
        const uint32_t b_base1 = b_base0 + TILEB;

#pragma unroll
        for (int ks = 0; ks < KC / 16; ks++) {
            uint32_t Af[2][4][4];
            uint32_t Bf[2][4][2];
#pragma unroll
            for (int mi = 0; mi < 4; mi++) {
                LDSM_X4(Af[0][mi][0], Af[0][mi][1], Af[0][mi][2], Af[0][mi][3],
                        a_base0 + (uint32_t)mi * 16 * ROWB + ks * 32);
                LDSM_X4(Af[1][mi][0], Af[1][mi][1], Af[1][mi][2], Af[1][mi][3],
                        a_base1 + (uint32_t)mi * 16 * ROWB + ks * 32);
            }
#pragma unroll
            for (int g = 0; g < 2; g++) {
                LDSM_X4(Bf[0][2*g][0], Bf[0][2*g][1], Bf[0][2*g+1][0], Bf[0][2*g+1][1],
                        b_base0 + (uint32_t)g * 16 * ROWB + ks * 32);
                LDSM_X4(Bf[1][2*g][0], Bf[1][2*g][1], Bf[1][2*g+1][0], Bf[1][2*g+1][1],
                        b_base1 + (uint32_t)g * 16 * ROWB + ks * 32);
            }
#pragma unroll
            for (int mi = 0; mi < 4; mi++)
#pragma unroll
                for (int ni = 0; ni < 4; ni++) {
                    MMA16816(acc[mi][ni][0], acc[mi][ni][1], acc[mi][ni][2], acc[mi][ni][3],
                             Af[0][mi][0], Af[0][mi][1], Af[0][mi][2], Af[0][mi][3],
                             Bf[0][ni][0], Bf[0][ni][1]);
                    MMA16816(acc[mi][ni][0], acc[mi][ni][1], acc[mi][ni][2], acc[mi][ni][3],
                             Af[0][mi][0], Af[0][mi][1], Af[0][mi][2], Af[0][mi][3],
                             Bf[1][ni][0], Bf[1][ni][1]);
                    MMA16816(acc[mi][ni][0], acc[mi][ni][1], acc[mi][ni][2], acc[mi][ni][3],
                             Af[1][mi][0], Af[1][mi][1], Af[1][mi][2], Af[1][mi][3],
                             Bf[0][ni][0], Bf[0][ni][1]);
                }
        }
        __syncthreads();
    }

#pragma unroll
    for (int mi = 0; mi < 4; mi++) {
        const int r0 = block_row + m_off + mi * 16 + (lane >> 2);
        const int r1 = r0 + 8;
#pragma unroll
        for (int ni = 0; ni < 4; ni++) {
            const int col = block_col + n_off + ni * 8 + (lane & 3) * 2;
            const float c0 = __ldg(cvec + col);
            const float c1 = __ldg(cvec + col + 1);
            float2 o0 = {acc[mi][ni][0] + c0, acc[mi][ni][1] + c1};
            float2 o1 = {acc[mi][ni][2] + c0, acc[mi][ni][3] + c1};
            *(float2*)(g_pre + (size_t)r0 * NHID + col) = o0;
            *(float2*)(g_pre + (size_t)r1 * NHID + col) = o1;
            // mask = 1[p > 21]  (bitwise-consistent with fenergy's classification)
            __nv_bfloat162 m0, m1;
            m0.x = __float2bfloat16(o0.x > 21.0f ? 1.0f : 0.0f);
            m0.y = __float2bfloat16(o0.y > 21.0f ? 1.0f : 0.0f);
            m1.x = __float2bfloat16(o1.x > 21.0f ? 1.0f : 0.0f);
            m1.y = __float2bfloat16(o1.y > 21.0f ? 1.0f : 0.0f);
            *(__nv_bfloat162*)(g_mask + (size_t)r0 * NHID + col) = m0;
            *(__nv_bfloat162*)(g_mask + (size_t)r1 * NHID + col) = m1;
        }
    }
}

// ---------------------------------------------------------------------------
// K1b: mask-GEMM  G_part[kq][b][y] = sum_{j in kq-range} M[b][j] * U[y][j]
// (3-limb U). Grid (4 split-K, 16 M-blocks), 256 threads, 2-stage cp.async.
// ---------------------------------------------------------------------------
#define MG_TA   (128 * ROWB)             // M tile (128 rows)
#define MG_TU   (64 * ROWB)              // U limb tile (64 rows)
#define MG_BUF  (MG_TA + 3 * MG_TU)      // 46080
#define MG_SMEM (2 * MG_BUF)             // 92160

__global__ __launch_bounds__(256, 2) void maskgemm_kernel() {
    extern __shared__ char smem[];
    const int tid  = threadIdx.x;
    const int wid  = tid >> 5;
    const int lane = tid & 31;
    const int block_row = blockIdx.y * 128;
    const int k_base    = blockIdx.x * 256;     // split-K range: 256 k's

    const __nv_bfloat16* usrc[3] = {g_uh, g_um, g_ul};

    auto load_chunk = [&](int k0, int stage) {
        char* bufp = smem + stage * MG_BUF;
#pragma unroll
        for (int i = 0; i < 4; i++) {
            int idx = i * 256 + tid;
            int r = idx >> 3, c = idx & 7;
            CP_ASYNC(smem_u32(bufp + r * ROWB + c * 16),
                     g_mask + (size_t)(block_row + r) * NHID + k0 + c * 8);
        }
#pragma unroll
        for (int t = 0; t < 3; t++) {
#pragma unroll
            for (int i = 0; i < 2; i++) {
                int idx = i * 256 + tid;
                int r = idx >> 3, c = idx & 7;
                CP_ASYNC(smem_u32(bufp + MG_TA + t * MG_TU + r * ROWB + c * 16),
                         usrc[t] + (size_t)r * NHID + k0 + c * 8);
            }
        }
    };

    const int m_off = (wid & 3) * 32;
    const int n_off = (wid >> 2) * 32;

    const uint32_t a_lane = (uint32_t)(m_off + (lane & 15)) * ROWB + (lane >> 4) * 16;
    const uint32_t b_lane = (uint32_t)(n_off + ((lane >> 4) & 1) * 8 + (lane & 7)) * ROWB
                          + ((lane >> 3) & 1) * 16;

    float acc[2][4][4];
#pragma unroll
    for (int mi = 0; mi < 2; mi++)
#pragma unroll
        for (int ni = 0; ni < 4; ni++)
#pragma unroll
            for (int q = 0; q < 4; q++) acc[mi][ni][q] = 0.0f;

    load_chunk(k_base, 0); CP_COMMIT();

    for (int ch = 0; ch < 4; ch++) {                 // 4 chunks of KC=64
        if (ch + 1 < 4) { load_chunk(k_base + (ch + 1) * KC, (ch + 1) & 1); CP_COMMIT(); CP_WAIT(1); }
        else            { CP_WAIT(0); }
        __syncthreads();

        const char* bufp = smem + (ch & 1) * MG_BUF;
        const uint32_t a_base = smem_u32(bufp) + a_lane;
        const uint32_t b_base = smem_u32(bufp + MG_TA) + b_lane;

#pragma unroll
        for (int ks = 0; ks < KC / 16; ks++) {
            uint32_t Af[2][4];
            uint32_t Bf[3][4][2];
#pragma unroll
            for (int mi = 0; mi < 2; mi++)
                LDSM_X4(Af[mi][0], Af[mi][1], Af[mi][2], Af[mi][3],
                        a_base + (uint32_t)mi * 16 * ROWB + ks * 32);
#pragma unroll
            for (int t = 0; t < 3; t++)
#pragma unroll
                for (int g = 0; g < 2; g++)
                    LDSM_X4(Bf[t][2*g][0], Bf[t][2*g][1], Bf[t][2*g+1][0], Bf[t][2*g+1][1],
                            b_base + t * MG_TU + (uint32_t)g * 16 * ROWB + ks * 32);
#pragma unroll
            for (int mi = 0; mi < 2; mi++)
#pragma unroll
                for (int ni = 0; ni < 4; ni++)
#pragma unroll
                    for (int t = 0; t < 3; t++)
                        MMA16816(acc[mi][ni][0], acc[mi][ni][1], acc[mi][ni][2], acc[mi][ni][3],
                                 Af[mi][0], Af[mi][1], Af[mi][2], Af[mi][3],
                                 Bf[t][ni][0], Bf[t][ni][1]);
        }
        __syncthreads();
    }

    float* gout = g_G + (size_t)blockIdx.x * B_DIM * NCLASS;
#pragma unroll
    for (int mi = 0; mi < 2; mi++) {
        const int r0 = block_row + m_off + mi * 16 + (lane >> 2);
        const int r1 = r0 + 8;
#pragma unroll
        for (int ni = 0; ni < 4; ni++) {
            const int col = n_off + ni * 8 + (lane & 3) * 2;
            *(float2*)(gout + (size_t)r0 * NCLASS + col) =
                make_float2(acc[mi][ni][0], acc[mi][ni][1]);
            *(float2*)(gout + (size_t)r1 * NCLASS + col) =
                make_float2(acc[mi][ni][2], acc[mi][ni][3]);
        }
    }
}

// ---------------------------------------------------------------------------
// K2: slow-only fenergy. F[b,y] (mod row-const) = G[b,y] + d_y
//     + sum_{|p|<=21} softplus(p + u_yj). 8 rows/CTA, warp = row.
// ---------------------------------------------------------------------------
#define TJ 128
#define UPAD 133

__global__ __launch_bounds__(256) void fenergy_kernel(const float* __restrict__ dvec,
                                                      const float* __restrict__ U,
                                                      float* __restrict__ out) {
    __shared__ float  Us[64 * UPAD];
    __shared__ float  ps[8][TJ];
    __shared__ float2 slist[8][TJ];

    const int tid  = threadIdx.x;
    const int wid  = tid >> 5;
    const int lane = tid & 31;
    const int b0   = blockIdx.x * 8;
    const int y0   = lane;
    const int y1   = lane + 32;

    const float* urow0 = &Us[y0 * UPAD];
    const float* urow1 = &Us[y1 * UPAD];

    const float LOG2E = 1.4426950408889634f;
    const float LN2   = 0.6931471805599453f;

    float acc0 = 0.0f, acc1 = 0.0f;

    for (int j0 = 0; j0 < NHID; j0 += TJ) {
#pragma unroll
        for (int i = 0; i < 8; i++) {
            int e  = i * 256 + tid;
            int yy = e >> 5;
            int jq = (e & 31) * 4;
            float4 u4 = *(const float4*)(U + (size_t)yy * NHID + j0 + jq);
            float* dst = &Us[yy * UPAD + jq];
            dst[0] = u4.x; dst[1] = u4.y; dst[2] = u4.z; dst[3] = u4.w;
        }
        {
            int bb = tid >> 5;
            int jq = (tid & 31) * 4;
            float4 p4 = *(const float4*)(g_pre + (size_t)(b0 + bb) * NHID + j0 + jq);
            *(float4*)&ps[bb][jq] = p4;
        }
        __syncthreads();

        // slow list: |p| <= 21 (complement of mask p>21 and drop p<-21)
        int cnt = 0;
#pragma unroll
        for (int s = 0; s < 4; s++) {
            int jj = s * 32 + lane;
            float p = ps[wid][jj];
            bool slow = fabsf(p) <= 21.0f;
            unsigned mask = __ballot_sync(0xffffffffu, slow);
            int rank = __popc(mask & ((1u << lane) - 1u));
            if (slow) slist[wid][cnt + rank] = make_float2(__int_as_float(jj), p);
            cnt += __popc(mask);
        }

        // slow-only full softplus: max(x,0) + ln(1+e^-|x|) (log-product trick)
        float a0 = 0.f, a1 = 0.f;
        float c0 = 0.f, c1 = 0.f;
        float P0 = 1.f, P1 = 1.f;
        for (int i = 0; i < cnt; i++) {
            float2 e = slist[wid][i];
            int jj  = __float_as_int(e.x);
            float p = e.y;
            float x0 = p + urow0[jj];
            float x1 = p + urow1[jj];
            a0 += fmaxf(x0, 0.f);
            a1 += fmaxf(x1, 0.f);
            float u0 = exp2f(-fabsf(x0) * LOG2E);
            float u1 = exp2f(-fabsf(x1) * LOG2E);
            P0 = fmaf(P0, u0, P0);
            P1 = fmaf(P1, u1, P1);
            if ((i & 31) == 31) {
                c0 += __log2f(P0); P0 = 1.f;
                c1 += __log2f(P1); P1 = 1.f;
            }
        }
        c0 += __log2f(P0);
        c1 += __log2f(P1);

        acc0 += a0 + LN2 * c0;
        acc1 += a1 + LN2 * c1;
        __syncthreads();
    }

    // add mask-GEMM parts (fast+ u-sums) and d; row-constant S_b dropped
    const int b = b0 + wid;
    float gg0 = 0.f, gg1 = 0.f;
#pragma unroll
    for (int q = 0; q < 4; q++) {
        gg0 += g_G[(size_t)q * B_DIM * NCLASS + (size_t)b * NCLASS + y0];
        gg1 += g_G[(size_t)q * B_DIM * NCLASS + (size_t)b * NCLASS + y1];
    }
    float f0 = acc0 + gg0 + __ldg(dvec + y0);
    float f1 = acc1 + gg1 + __ldg(dvec + y1);

    float m = fmaxf(f0, f1);
#pragma unroll
    for (int o = 16; o > 0; o >>= 1) m = fmaxf(m, __shfl_xor_sync(0xffffffffu, m, o));
    float e0 = __expf(f0 - m);
    float e1 = __expf(f1 - m);
    float s = e0 + e1;
#pragma unroll
    for (int o = 16; o > 0; o >>= 1) s += __shfl_xor_sync(0xffffffffu, s, o);
    float inv = 1.0f / s;
    float p0 = e0 * inv;
    float p1 = e1 * inv;

    float pm = p0; int im = y0;
    if (p1 > pm) { pm = p1; im = y1; }
#pragma unroll
    for (int o = 16; o > 0; o >>= 1) {
        float po = __shfl_xor_sync(0xffffffffu, pm, o);
        int   io = __shfl_xor_sync(0xffffffffu, im, o);
        if (po > pm || (po == pm && io < im)) { pm = po; im = io; }
    }

    out[(size_t)b * NCLASS + y0] = p0;
    out[(size_t)b * NCLASS + y1] = p1;
    float* oh = out + (size_t)B_DIM * NCLASS;
    oh[(size_t)b * NCLASS + y0] = (y0 == im) ? 1.0f : 0.0f;
    oh[(size_t)b * NCLASS + y1] = (y1 == im) ? 1.0f : 0.0f;
}

// ---------------------------------------------------------------------------
extern "C" void kernel_launch(void* const* d_in, const int* in_sizes, int n_in,
                              void* d_out, int out_size) {
    const float* v = (const float*)d_in[0];
    const float* W = (const float*)d_in[1];
    const float* c = (const float*)d_in[2];
    const float* d = (const float*)d_in[3];
    const float* U = (const float*)d_in[4];
    float* out = (float*)d_out;

    cudaFuncSetAttribute(gemm_mma_kernel,
                         cudaFuncAttributeMaxDynamicSharedMemorySize, GEMM_SMEM);
    cudaFuncSetAttribute(maskgemm_kernel,
                         cudaFuncAttributeMaxDynamicSharedMemorySize, MG_SMEM);

    split_kernel<<<3088, 256>>>(v, W, U);
    gemm_mma_kernel<<<dim3(NHID / 128, B_DIM / 128), 256, GEMM_SMEM>>>(c);
    maskgemm_kernel<<<dim3(4, B_DIM / 128), 256, MG_SMEM>>>();
    fenergy_kernel<<<B_DIM / 8, 256>>>(d, U, out);
}